// round 1
// baseline (speedup 1.0000x reference)
#include <cuda_runtime.h>
#include <cuda_bf16.h>

#define N_NODES 1200000
#define E_EDGES 12000000
#define D_IN    10
#define D_H     20
#define D_ENC   5
#define VEC     6
#define B_ROWS  200000

// Scratch (device globals — allocation-free per harness rules)
__device__ float g_deg [N_NODES];
__device__ float g_dinv[N_NODES];
__device__ float g_h   [N_NODES * D_H];   // xW1 (gather source, layer 1)
__device__ float g_agg [N_NODES * D_H];   // layer-1 accumulator
__device__ float g_h2  [N_NODES * 8];     // h1W2 padded to stride 8 (gather source, layer 2)
__device__ float g_agg2[N_NODES * 8];     // layer-2 accumulator

__device__ __forceinline__ float gelu_exact(float v) {
    // exact gelu: x * Phi(x)
    return v * normcdff(v);
}

__device__ __forceinline__ void red_add_v4(float* p, float a, float b, float c, float d) {
    asm volatile("red.global.add.v4.f32 [%0], {%1,%2,%3,%4};"
                 :: "l"(p), "f"(a), "f"(b), "f"(c), "f"(d) : "memory");
}
__device__ __forceinline__ void red_add_f32(float* p, float a) {
    asm volatile("red.global.add.f32 [%0], %1;" :: "l"(p), "f"(a) : "memory");
}

// ---------------------------------------------------------------- kernels

__global__ void k_zero_deg() {
    int i = blockIdx.x * blockDim.x + threadIdx.x;
    if (i < N_NODES) g_deg[i] = 0.0f;
}

__global__ void k_deg(const int* __restrict__ ei) {
    int e = blockIdx.x * blockDim.x + threadIdx.x;
    if (e < E_EDGES) {
        int dst = ei[E_EDGES + e];
        atomicAdd(&g_deg[dst], 1.0f);
    }
}

// dinv + h = (x+po)@W1 ; agg init = h*dinv^2
__global__ void k_node1(const float* __restrict__ x, const float* __restrict__ W1) {
    __shared__ float sW[D_IN * D_H];   // 200
    if (threadIdx.x < D_IN * D_H) sW[threadIdx.x] = W1[threadIdx.x];
    __syncthreads();

    int i = blockIdx.x * blockDim.x + threadIdx.x;
    if (i >= N_NODES) return;

    float dinv = rsqrtf(g_deg[i] + 1.0f);
    g_dinv[i] = dinv;
    float d2 = dinv * dinv;

    float xi[D_IN];
#pragma unroll
    for (int j = 0; j < D_IN; j++) xi[j] = x[i * D_IN + j] + sinf((float)j);

    float h[D_H];
#pragma unroll
    for (int k = 0; k < D_H; k++) {
        float s = 0.0f;
#pragma unroll
        for (int j = 0; j < D_IN; j++) s = fmaf(xi[j], sW[j * D_H + k], s);
        h[k] = s;
    }

    float4* ph = reinterpret_cast<float4*>(g_h   + i * D_H);  // 80B rows, 16B aligned
    float4* pa = reinterpret_cast<float4*>(g_agg + i * D_H);
#pragma unroll
    for (int q = 0; q < 5; q++) {
        float4 v = make_float4(h[q*4+0], h[q*4+1], h[q*4+2], h[q*4+3]);
        ph[q] = v;
        pa[q] = make_float4(v.x * d2, v.y * d2, v.z * d2, v.w * d2);
    }
}

// layer-1 edge scatter: agg[dst] += h[src] * dinv[src]*dinv[dst]
__global__ void k_edge1(const int* __restrict__ ei) {
    int e = blockIdx.x * blockDim.x + threadIdx.x;
    if (e >= E_EDGES) return;
    int s = ei[e];
    int d = ei[E_EDGES + e];
    float norm = g_dinv[s] * g_dinv[d];
    const float4* hs = reinterpret_cast<const float4*>(g_h + (size_t)s * D_H);
    float* ad = g_agg + (size_t)d * D_H;
#pragma unroll
    for (int q = 0; q < 5; q++) {
        float4 v = hs[q];
        red_add_v4(ad + q * 4, v.x * norm, v.y * norm, v.z * norm, v.w * norm);
    }
}

// h1 = gelu(agg+b1); h2 = h1@W2 ; agg2 init = h2*dinv^2   (stride-8 rows)
__global__ void k_node2(const float* __restrict__ b1, const float* __restrict__ W2) {
    __shared__ float sW[D_H * D_ENC];  // 100
    __shared__ float sb[D_H];
    if (threadIdx.x < D_H * D_ENC) sW[threadIdx.x] = W2[threadIdx.x];
    if (threadIdx.x < D_H) sb[threadIdx.x] = b1[threadIdx.x];
    __syncthreads();

    int i = blockIdx.x * blockDim.x + threadIdx.x;
    if (i >= N_NODES) return;

    float h1[D_H];
#pragma unroll
    for (int k = 0; k < D_H; k++)
        h1[k] = gelu_exact(g_agg[(size_t)i * D_H + k] + sb[k]);

    float h2[D_ENC];
#pragma unroll
    for (int c = 0; c < D_ENC; c++) {
        float s = 0.0f;
#pragma unroll
        for (int k = 0; k < D_H; k++) s = fmaf(h1[k], sW[k * D_ENC + c], s);
        h2[c] = s;
    }

    float dv = g_dinv[i];
    float d2 = dv * dv;
    float* ph = g_h2   + (size_t)i * 8;
    float* pa = g_agg2 + (size_t)i * 8;
    *reinterpret_cast<float4*>(ph) = make_float4(h2[0], h2[1], h2[2], h2[3]);
    ph[4] = h2[4];
    *reinterpret_cast<float4*>(pa) = make_float4(h2[0]*d2, h2[1]*d2, h2[2]*d2, h2[3]*d2);
    pa[4] = h2[4] * d2;
}

// layer-2 edge scatter
__global__ void k_edge2(const int* __restrict__ ei) {
    int e = blockIdx.x * blockDim.x + threadIdx.x;
    if (e >= E_EDGES) return;
    int s = ei[e];
    int d = ei[E_EDGES + e];
    float norm = g_dinv[s] * g_dinv[d];
    const float* hs = g_h2 + (size_t)s * 8;
    float* ad = g_agg2 + (size_t)d * 8;
    float4 v = *reinterpret_cast<const float4*>(hs);
    float v4 = hs[4];
    red_add_v4(ad, v.x * norm, v.y * norm, v.z * norm, v.w * norm);
    red_add_f32(ad + 4, v4 * norm);
}

// epilogue: h2 = gelu(agg2+b2) -> r[30] -> enc/x1/out
__global__ void k_final(const float* __restrict__ b2,
                        const float* __restrict__ We, const float* __restrict__ be,
                        const float* __restrict__ Wd, const float* __restrict__ bd,
                        const float* __restrict__ Wr, const float* __restrict__ br,
                        float* __restrict__ out) {
    __shared__ float sWe[30 * 30];
    __shared__ float sWd[30 * 60];
    __shared__ float sWr[30 * 7];
    __shared__ float sbe[30], sbd[60], sbr[7], sb2[5];

    for (int t = threadIdx.x; t < 900;  t += blockDim.x) sWe[t] = We[t];
    for (int t = threadIdx.x; t < 1800; t += blockDim.x) sWd[t] = Wd[t];
    for (int t = threadIdx.x; t < 210;  t += blockDim.x) sWr[t] = Wr[t];
    if (threadIdx.x < 30) sbe[threadIdx.x] = be[threadIdx.x];
    if (threadIdx.x < 60) sbd[threadIdx.x] = bd[threadIdx.x];
    if (threadIdx.x < 7)  sbr[threadIdx.x] = br[threadIdx.x];
    if (threadIdx.x < 5)  sb2[threadIdx.x] = b2[threadIdx.x];
    __syncthreads();

    int b = blockIdx.x * blockDim.x + threadIdx.x;
    if (b >= B_ROWS) return;

    float r[30];
#pragma unroll
    for (int v = 0; v < VEC; v++) {
        const float* pa = g_agg2 + (size_t)(b * VEC + v) * 8;
#pragma unroll
        for (int k = 0; k < D_ENC; k++)
            r[v * D_ENC + k] = gelu_exact(pa[k] + sb2[k]);
    }

    float enc[30];
#pragma unroll
    for (int o = 0; o < 30; o++) {
        float s = sbe[o];
#pragma unroll
        for (int j = 0; j < 30; j++) s = fmaf(r[j], sWe[j * 30 + o], s);
        enc[o] = s;
    }

    // x1 = enc@Wr + br  -> region [0, B*7)
    float* px1 = out + (size_t)b * 7;
#pragma unroll
    for (int o = 0; o < 7; o++) {
        float s = sbr[o];
#pragma unroll
        for (int j = 0; j < 30; j++) s = fmaf(enc[j], sWr[j * 7 + o], s);
        px1[o] = s;
    }

    // enc -> region [B*7, B*7 + B*30)
    float* pe = out + (size_t)B_ROWS * 7 + (size_t)b * 30;
#pragma unroll
    for (int o = 0; o < 30; o++) pe[o] = enc[o];

    // out = gelu(enc)@Wd + bd -> region [B*37, B*97)
#pragma unroll
    for (int j = 0; j < 30; j++) r[j] = gelu_exact(enc[j]);
    float* po = out + (size_t)B_ROWS * 37 + (size_t)b * 60;
#pragma unroll
    for (int o = 0; o < 60; o++) {
        float s = sbd[o];
#pragma unroll
        for (int j = 0; j < 30; j++) s = fmaf(r[j], sWd[j * 60 + o], s);
        po[o] = s;
    }
}

// ---------------------------------------------------------------- launch

extern "C" void kernel_launch(void* const* d_in, const int* in_sizes, int n_in,
                              void* d_out, int out_size) {
    const float* x  = (const float*)d_in[0];
    const int*   ei = (const int*)  d_in[1];
    const float* W1 = (const float*)d_in[2];
    const float* b1 = (const float*)d_in[3];
    const float* W2 = (const float*)d_in[4];
    const float* b2 = (const float*)d_in[5];
    const float* We = (const float*)d_in[6];
    const float* be = (const float*)d_in[7];
    const float* Wd = (const float*)d_in[8];
    const float* bd = (const float*)d_in[9];
    const float* Wr = (const float*)d_in[10];
    const float* br = (const float*)d_in[11];
    float* out = (float*)d_out;

    const int TB = 256;
    int gN = (N_NODES + TB - 1) / TB;
    int gE = (E_EDGES + TB - 1) / TB;
    int gB = (B_ROWS + TB - 1) / TB;

    k_zero_deg<<<gN, TB>>>();
    k_deg<<<gE, TB>>>(ei);
    k_node1<<<gN, TB>>>(x, W1);
    k_edge1<<<gE, TB>>>(ei);
    k_node2<<<gN, TB>>>(b1, W2);
    k_edge2<<<gE, TB>>>(ei);
    k_final<<<gB, TB>>>(b2, We, be, Wd, bd, Wr, br, out);
}

// round 2
// speedup vs baseline: 1.1545x; 1.1545x over previous
#include <cuda_runtime.h>
#include <cuda_fp16.h>
#include <cuda_bf16.h>

#define N_NODES 1200000
#define E_EDGES 12000000
#define D_IN    10
#define D_H     20
#define D_ENC   5
#define VEC     6
#define B_ROWS  200000

// ---- scratch (device globals; allocation-free) ----
__device__ float  g_deg [N_NODES];
__device__ float  g_dinv[N_NODES];
// layer-1 h split into 2 halves of 10 cols each, fp16, padded to 16 halfs (32B rows)
__device__ __half g_hh  [2][N_NODES * 16];
// layer-1 accumulator split likewise, f32, padded to 12 floats (48B rows, 16B aligned)
__device__ float  g_agg [2][N_NODES * 12];
// layer-2 h fp16, 5 cols padded to 8 halfs (16B rows)
__device__ __half g_h2h [N_NODES * 8];
// layer-2 accumulator f32, stride 8 (32B rows)
__device__ float  g_agg2[N_NODES * 8];

__device__ __forceinline__ float gelu_exact(float v) { return v * normcdff(v); }

__device__ __forceinline__ void red_add_v4(float* p, float a, float b, float c, float d) {
    asm volatile("red.global.add.v4.f32 [%0], {%1,%2,%3,%4};"
                 :: "l"(p), "f"(a), "f"(b), "f"(c), "f"(d) : "memory");
}
__device__ __forceinline__ void red_add_v2(float* p, float a, float b) {
    asm volatile("red.global.add.v2.f32 [%0], {%1,%2};"
                 :: "l"(p), "f"(a), "f"(b) : "memory");
}
__device__ __forceinline__ void red_add_f32(float* p, float a) {
    asm volatile("red.global.add.f32 [%0], %1;" :: "l"(p), "f"(a) : "memory");
}

// ---------------------------------------------------------------- kernels

__global__ void k_zero_deg() {
    int i = blockIdx.x * blockDim.x + threadIdx.x;
    if (i < N_NODES) g_deg[i] = 0.0f;
}

__global__ void k_deg(const int* __restrict__ ei) {
    int e = blockIdx.x * blockDim.x + threadIdx.x;
    if (e < E_EDGES) {
        int dst = __ldcs(ei + E_EDGES + e);
        atomicAdd(&g_deg[dst], 1.0f);
    }
}

// dinv + h = (x+po)@W1 ; write fp16 halves + f32 agg init (self-loop term)
__global__ void k_node1(const float* __restrict__ x, const float* __restrict__ W1) {
    __shared__ float sW[D_IN * D_H];
    if (threadIdx.x < D_IN * D_H) sW[threadIdx.x] = W1[threadIdx.x];
    __syncthreads();

    int i = blockIdx.x * blockDim.x + threadIdx.x;
    if (i >= N_NODES) return;

    float dinv = rsqrtf(g_deg[i] + 1.0f);
    g_dinv[i] = dinv;
    float d2 = dinv * dinv;

    float xi[D_IN];
#pragma unroll
    for (int j = 0; j < D_IN; j++) xi[j] = x[(size_t)i * D_IN + j] + sinf((float)j);

    float h[D_H];
#pragma unroll
    for (int k = 0; k < D_H; k++) {
        float s = 0.0f;
#pragma unroll
        for (int j = 0; j < D_IN; j++) s = fmaf(xi[j], sW[j * D_H + k], s);
        h[k] = s;
    }

#pragma unroll
    for (int p = 0; p < 2; p++) {
        // fp16 half-row: 10 halfs in a 32B row -> uint4 + uint
        __half hv[12];
#pragma unroll
        for (int k = 0; k < 10; k++) hv[k] = __float2half_rn(h[p * 10 + k]);
        hv[10] = __float2half_rn(0.f); hv[11] = __float2half_rn(0.f);
        uint4 w0 = *reinterpret_cast<const uint4*>(&hv[0]);
        unsigned w1 = *reinterpret_cast<const unsigned*>(&hv[8]);
        __half* hp = &g_hh[p][(size_t)i * 16];
        *reinterpret_cast<uint4*>(hp) = w0;
        *reinterpret_cast<unsigned*>(hp + 8) = w1;

        float* ap = &g_agg[p][(size_t)i * 12];
        *reinterpret_cast<float4*>(ap) =
            make_float4(h[p*10+0]*d2, h[p*10+1]*d2, h[p*10+2]*d2, h[p*10+3]*d2);
        *reinterpret_cast<float4*>(ap + 4) =
            make_float4(h[p*10+4]*d2, h[p*10+5]*d2, h[p*10+6]*d2, h[p*10+7]*d2);
        *reinterpret_cast<float2*>(ap + 8) =
            make_float2(h[p*10+8]*d2, h[p*10+9]*d2);
    }
}

// layer-1 edge scatter, one feature half per pass (L2-resident working set)
template <int P>
__global__ void k_edge1(const int* __restrict__ ei) {
    int e = blockIdx.x * blockDim.x + threadIdx.x;
    if (e >= E_EDGES) return;
    int s = __ldcs(ei + e);
    int d = __ldcs(ei + E_EDGES + e);
    float norm = g_dinv[s] * g_dinv[d];

    const __half* hp = &g_hh[P][(size_t)s * 16];
    uint4 w0 = *reinterpret_cast<const uint4*>(hp);
    unsigned w1 = *reinterpret_cast<const unsigned*>(hp + 8);
    const __half2* h2p = reinterpret_cast<const __half2*>(&w0);
    float2 f0 = __half22float2(h2p[0]);
    float2 f1 = __half22float2(h2p[1]);
    float2 f2 = __half22float2(h2p[2]);
    float2 f3 = __half22float2(h2p[3]);
    float2 f4 = __half22float2(*reinterpret_cast<const __half2*>(&w1));

    float* ad = &g_agg[P][(size_t)d * 12];
    red_add_v4(ad,     f0.x * norm, f0.y * norm, f1.x * norm, f1.y * norm);
    red_add_v4(ad + 4, f2.x * norm, f2.y * norm, f3.x * norm, f3.y * norm);
    red_add_v2(ad + 8, f4.x * norm, f4.y * norm);
}

// h1 = gelu(agg+b1); h2 = h1@W2 ; write fp16 h2 + f32 agg2 init
__global__ void k_node2(const float* __restrict__ b1, const float* __restrict__ W2) {
    __shared__ float sW[D_H * D_ENC];
    __shared__ float sb[D_H];
    if (threadIdx.x < D_H * D_ENC) sW[threadIdx.x] = W2[threadIdx.x];
    if (threadIdx.x < D_H) sb[threadIdx.x] = b1[threadIdx.x];
    __syncthreads();

    int i = blockIdx.x * blockDim.x + threadIdx.x;
    if (i >= N_NODES) return;

    float h1[D_H];
#pragma unroll
    for (int p = 0; p < 2; p++) {
        const float* ap = &g_agg[p][(size_t)i * 12];
#pragma unroll
        for (int k = 0; k < 10; k++)
            h1[p * 10 + k] = gelu_exact(ap[k] + sb[p * 10 + k]);
    }

    float h2[D_ENC];
#pragma unroll
    for (int c = 0; c < D_ENC; c++) {
        float s = 0.0f;
#pragma unroll
        for (int k = 0; k < D_H; k++) s = fmaf(h1[k], sW[k * D_ENC + c], s);
        h2[c] = s;
    }

    float dv = g_dinv[i];
    float d2 = dv * dv;

    __half hv[8];
#pragma unroll
    for (int k = 0; k < D_ENC; k++) hv[k] = __float2half_rn(h2[k]);
#pragma unroll
    for (int k = D_ENC; k < 8; k++) hv[k] = __float2half_rn(0.f);
    *reinterpret_cast<uint4*>(&g_h2h[(size_t)i * 8]) = *reinterpret_cast<const uint4*>(hv);

    float* pa = &g_agg2[(size_t)i * 8];
    *reinterpret_cast<float4*>(pa) = make_float4(h2[0]*d2, h2[1]*d2, h2[2]*d2, h2[3]*d2);
    pa[4] = h2[4] * d2;
}

// layer-2 edge scatter (fully L2-resident)
__global__ void k_edge2(const int* __restrict__ ei) {
    int e = blockIdx.x * blockDim.x + threadIdx.x;
    if (e >= E_EDGES) return;
    int s = __ldcs(ei + e);
    int d = __ldcs(ei + E_EDGES + e);
    float norm = g_dinv[s] * g_dinv[d];

    uint4 w = *reinterpret_cast<const uint4*>(&g_h2h[(size_t)s * 8]);
    const __half2* h2p = reinterpret_cast<const __half2*>(&w);
    float2 f0 = __half22float2(h2p[0]);
    float2 f1 = __half22float2(h2p[1]);
    float2 f2 = __half22float2(h2p[2]);

    float* ad = &g_agg2[(size_t)d * 8];
    red_add_v4(ad, f0.x * norm, f0.y * norm, f1.x * norm, f1.y * norm);
    red_add_f32(ad + 4, f2.x * norm);
}

// epilogue
__global__ void k_final(const float* __restrict__ b2,
                        const float* __restrict__ We, const float* __restrict__ be,
                        const float* __restrict__ Wd, const float* __restrict__ bd,
                        const float* __restrict__ Wr, const float* __restrict__ br,
                        float* __restrict__ out) {
    __shared__ float sWe[30 * 30];
    __shared__ float sWd[30 * 60];
    __shared__ float sWr[30 * 7];
    __shared__ float sbe[30], sbd[60], sbr[7], sb2[5];

    for (int t = threadIdx.x; t < 900;  t += blockDim.x) sWe[t] = We[t];
    for (int t = threadIdx.x; t < 1800; t += blockDim.x) sWd[t] = Wd[t];
    for (int t = threadIdx.x; t < 210;  t += blockDim.x) sWr[t] = Wr[t];
    if (threadIdx.x < 30) sbe[threadIdx.x] = be[threadIdx.x];
    if (threadIdx.x < 60) sbd[threadIdx.x] = bd[threadIdx.x];
    if (threadIdx.x < 7)  sbr[threadIdx.x] = br[threadIdx.x];
    if (threadIdx.x < 5)  sb2[threadIdx.x] = b2[threadIdx.x];
    __syncthreads();

    int b = blockIdx.x * blockDim.x + threadIdx.x;
    if (b >= B_ROWS) return;

    float r[30];
#pragma unroll
    for (int v = 0; v < VEC; v++) {
        const float* pa = g_agg2 + (size_t)(b * VEC + v) * 8;
#pragma unroll
        for (int k = 0; k < D_ENC; k++)
            r[v * D_ENC + k] = gelu_exact(pa[k] + sb2[k]);
    }

    float enc[30];
#pragma unroll
    for (int o = 0; o < 30; o++) {
        float s = sbe[o];
#pragma unroll
        for (int j = 0; j < 30; j++) s = fmaf(r[j], sWe[j * 30 + o], s);
        enc[o] = s;
    }

    float* px1 = out + (size_t)b * 7;
#pragma unroll
    for (int o = 0; o < 7; o++) {
        float s = sbr[o];
#pragma unroll
        for (int j = 0; j < 30; j++) s = fmaf(enc[j], sWr[j * 7 + o], s);
        px1[o] = s;
    }

    float* pe = out + (size_t)B_ROWS * 7 + (size_t)b * 30;
#pragma unroll
    for (int o = 0; o < 30; o++) pe[o] = enc[o];

#pragma unroll
    for (int j = 0; j < 30; j++) r[j] = gelu_exact(enc[j]);
    float* po = out + (size_t)B_ROWS * 37 + (size_t)b * 60;
#pragma unroll
    for (int o = 0; o < 60; o++) {
        float s = sbd[o];
#pragma unroll
        for (int j = 0; j < 30; j++) s = fmaf(r[j], sWd[j * 60 + o], s);
        po[o] = s;
    }
}

// ---------------------------------------------------------------- launch

extern "C" void kernel_launch(void* const* d_in, const int* in_sizes, int n_in,
                              void* d_out, int out_size) {
    const float* x  = (const float*)d_in[0];
    const int*   ei = (const int*)  d_in[1];
    const float* W1 = (const float*)d_in[2];
    const float* b1 = (const float*)d_in[3];
    const float* W2 = (const float*)d_in[4];
    const float* b2 = (const float*)d_in[5];
    const float* We = (const float*)d_in[6];
    const float* be = (const float*)d_in[7];
    const float* Wd = (const float*)d_in[8];
    const float* bd = (const float*)d_in[9];
    const float* Wr = (const float*)d_in[10];
    const float* br = (const float*)d_in[11];
    float* out = (float*)d_out;

    const int TB = 256;
    int gN = (N_NODES + TB - 1) / TB;
    int gE = (E_EDGES + TB - 1) / TB;
    int gB = (B_ROWS + TB - 1) / TB;

    k_zero_deg<<<gN, TB>>>();
    k_deg<<<gE, TB>>>(ei);
    k_node1<<<gN, TB>>>(x, W1);
    k_edge1<0><<<gE, TB>>>(ei);
    k_edge1<1><<<gE, TB>>>(ei);
    k_node2<<<gN, TB>>>(b1, W2);
    k_edge2<<<gE, TB>>>(ei);
    k_final<<<gB, TB>>>(b2, We, be, Wd, bd, Wr, br, out);
}

// round 3
// speedup vs baseline: 1.3786x; 1.1941x over previous
#include <cuda_runtime.h>
#include <cuda_fp16.h>
#include <cuda_bf16.h>

#define N_NODES 1200000
#define E_EDGES 12000000
#define D_IN    10
#define D_H     20
#define D_ENC   5
#define VEC     6
#define B_ROWS  200000

// ---- scratch (device globals; allocation-free) ----
__device__ float  g_deg [N_NODES];
__device__ float  g_dinv[N_NODES];
// layer-1 gather source: (h * dinv) split into 2 halves of 10 cols, fp16, 32B rows
__device__ __half g_hh  [2][N_NODES * 16];
// layer-1 accumulator split likewise, f32, 12-float rows (16B-aligned for red.v4)
__device__ float  g_agg [2][N_NODES * 12];
// layer-2 gather source: (h2 * dinv), fp16, 16B rows
__device__ __half g_h2h [N_NODES * 8];
// layer-2 accumulator f32, stride 8
__device__ float  g_agg2[N_NODES * 8];

__device__ __forceinline__ float gelu_exact(float v) { return v * normcdff(v); }

__device__ __forceinline__ void red_add_v4(float* p, float a, float b, float c, float d) {
    asm volatile("red.global.add.v4.f32 [%0], {%1,%2,%3,%4};"
                 :: "l"(p), "f"(a), "f"(b), "f"(c), "f"(d) : "memory");
}
__device__ __forceinline__ void red_add_v2(float* p, float a, float b) {
    asm volatile("red.global.add.v2.f32 [%0], {%1,%2};"
                 :: "l"(p), "f"(a), "f"(b) : "memory");
}
__device__ __forceinline__ void red_add_f32(float* p, float a) {
    asm volatile("red.global.add.f32 [%0], %1;" :: "l"(p), "f"(a) : "memory");
}

// ---------------------------------------------------------------- kernels

__global__ void k_zero_deg() {
    int i = blockIdx.x * blockDim.x + threadIdx.x;
    if (i < N_NODES) g_deg[i] = 0.0f;
}

__global__ void k_deg(const int* __restrict__ ei) {
    int e = blockIdx.x * blockDim.x + threadIdx.x;
    if (e < E_EDGES) {
        int dst = __ldcs(ei + E_EDGES + e);
        atomicAdd(&g_deg[dst], 1.0f);
    }
}

// dinv; h=(x+po)@W1; store h*dinv fp16 (gather src) + f32 agg init = h*dinv (self term)
__global__ void k_node1(const float* __restrict__ x, const float* __restrict__ W1) {
    __shared__ float sW[D_IN * D_H];
    if (threadIdx.x < D_IN * D_H) sW[threadIdx.x] = W1[threadIdx.x];
    __syncthreads();

    int i = blockIdx.x * blockDim.x + threadIdx.x;
    if (i >= N_NODES) return;

    float dinv = rsqrtf(g_deg[i] + 1.0f);
    g_dinv[i] = dinv;

    float xi[D_IN];
#pragma unroll
    for (int j = 0; j < D_IN; j++) xi[j] = x[(size_t)i * D_IN + j] + sinf((float)j);

    float h[D_H];
#pragma unroll
    for (int k = 0; k < D_H; k++) {
        float s = 0.0f;
#pragma unroll
        for (int j = 0; j < D_IN; j++) s = fmaf(xi[j], sW[j * D_H + k], s);
        h[k] = s * dinv;   // pre-scaled by source dinv
    }

#pragma unroll
    for (int p = 0; p < 2; p++) {
        __half hv[12];
#pragma unroll
        for (int k = 0; k < 10; k++) hv[k] = __float2half_rn(h[p * 10 + k]);
        hv[10] = __float2half_rn(0.f); hv[11] = __float2half_rn(0.f);
        __half* hp = &g_hh[p][(size_t)i * 16];
        *reinterpret_cast<uint4*>(hp)     = *reinterpret_cast<const uint4*>(&hv[0]);
        *reinterpret_cast<unsigned*>(hp + 8) = *reinterpret_cast<const unsigned*>(&hv[8]);

        float* ap = &g_agg[p][(size_t)i * 12];
        *reinterpret_cast<float4*>(ap) =
            make_float4(h[p*10+0], h[p*10+1], h[p*10+2], h[p*10+3]);
        *reinterpret_cast<float4*>(ap + 4) =
            make_float4(h[p*10+4], h[p*10+5], h[p*10+6], h[p*10+7]);
        *reinterpret_cast<float2*>(ap + 8) =
            make_float2(h[p*10+8], h[p*10+9]);
    }
}

// layer-1 edge scatter: pure gather -> RED (no dinv, no multiply)
template <int P>
__global__ void k_edge1(const int* __restrict__ ei) {
    int e = blockIdx.x * blockDim.x + threadIdx.x;
    if (e >= E_EDGES) return;
    int s = __ldcs(ei + e);
    int d = __ldcs(ei + E_EDGES + e);

    const __half* hp = &g_hh[P][(size_t)s * 16];
    uint4 w0 = *reinterpret_cast<const uint4*>(hp);
    unsigned w1 = *reinterpret_cast<const unsigned*>(hp + 8);
    const __half2* h2p = reinterpret_cast<const __half2*>(&w0);
    float2 f0 = __half22float2(h2p[0]);
    float2 f1 = __half22float2(h2p[1]);
    float2 f2 = __half22float2(h2p[2]);
    float2 f3 = __half22float2(h2p[3]);
    float2 f4 = __half22float2(*reinterpret_cast<const __half2*>(&w1));

    float* ad = &g_agg[P][(size_t)d * 12];
    red_add_v4(ad,     f0.x, f0.y, f1.x, f1.y);
    red_add_v4(ad + 4, f2.x, f2.y, f3.x, f3.y);
    red_add_v2(ad + 8, f4.x, f4.y);
}

// h1 = gelu(dinv*agg + b1); h2 = h1@W2; store h2*dinv fp16 + f32 agg2 init
__global__ void k_node2(const float* __restrict__ b1, const float* __restrict__ W2) {
    __shared__ float sW[D_H * D_ENC];
    __shared__ float sb[D_H];
    if (threadIdx.x < D_H * D_ENC) sW[threadIdx.x] = W2[threadIdx.x];
    if (threadIdx.x < D_H) sb[threadIdx.x] = b1[threadIdx.x];
    __syncthreads();

    int i = blockIdx.x * blockDim.x + threadIdx.x;
    if (i >= N_NODES) return;

    float dinv = g_dinv[i];

    float h1[D_H];
#pragma unroll
    for (int p = 0; p < 2; p++) {
        const float* ap = &g_agg[p][(size_t)i * 12];
#pragma unroll
        for (int k = 0; k < 10; k++)
            h1[p * 10 + k] = gelu_exact(fmaf(dinv, ap[k], sb[p * 10 + k]));
    }

    float h2[D_ENC];
#pragma unroll
    for (int c = 0; c < D_ENC; c++) {
        float s = 0.0f;
#pragma unroll
        for (int k = 0; k < D_H; k++) s = fmaf(h1[k], sW[k * D_ENC + c], s);
        h2[c] = s * dinv;   // pre-scaled by source dinv
    }

    __half hv[8];
#pragma unroll
    for (int k = 0; k < D_ENC; k++) hv[k] = __float2half_rn(h2[k]);
#pragma unroll
    for (int k = D_ENC; k < 8; k++) hv[k] = __float2half_rn(0.f);
    *reinterpret_cast<uint4*>(&g_h2h[(size_t)i * 8]) = *reinterpret_cast<const uint4*>(hv);

    float* pa = &g_agg2[(size_t)i * 8];
    *reinterpret_cast<float4*>(pa) = make_float4(h2[0], h2[1], h2[2], h2[3]);
    pa[4] = h2[4];
}

// layer-2 edge scatter: pure gather -> RED
__global__ void k_edge2(const int* __restrict__ ei) {
    int e = blockIdx.x * blockDim.x + threadIdx.x;
    if (e >= E_EDGES) return;
    int s = __ldcs(ei + e);
    int d = __ldcs(ei + E_EDGES + e);

    uint4 w = *reinterpret_cast<const uint4*>(&g_h2h[(size_t)s * 8]);
    const __half2* h2p = reinterpret_cast<const __half2*>(&w);
    float2 f0 = __half22float2(h2p[0]);
    float2 f1 = __half22float2(h2p[1]);
    float2 f2 = __half22float2(h2p[2]);

    float* ad = &g_agg2[(size_t)d * 8];
    red_add_v4(ad, f0.x, f0.y, f1.x, f1.y);
    red_add_f32(ad + 4, f2.x);
}

// epilogue
__global__ void k_final(const float* __restrict__ b2,
                        const float* __restrict__ We, const float* __restrict__ be,
                        const float* __restrict__ Wd, const float* __restrict__ bd,
                        const float* __restrict__ Wr, const float* __restrict__ br,
                        float* __restrict__ out) {
    __shared__ float sWe[30 * 30];
    __shared__ float sWd[30 * 60];
    __shared__ float sWr[30 * 7];
    __shared__ float sbe[30], sbd[60], sbr[7], sb2[5];

    for (int t = threadIdx.x; t < 900;  t += blockDim.x) sWe[t] = We[t];
    for (int t = threadIdx.x; t < 1800; t += blockDim.x) sWd[t] = Wd[t];
    for (int t = threadIdx.x; t < 210;  t += blockDim.x) sWr[t] = Wr[t];
    if (threadIdx.x < 30) sbe[threadIdx.x] = be[threadIdx.x];
    if (threadIdx.x < 60) sbd[threadIdx.x] = bd[threadIdx.x];
    if (threadIdx.x < 7)  sbr[threadIdx.x] = br[threadIdx.x];
    if (threadIdx.x < 5)  sb2[threadIdx.x] = b2[threadIdx.x];
    __syncthreads();

    int b = blockIdx.x * blockDim.x + threadIdx.x;
    if (b >= B_ROWS) return;

    float r[30];
#pragma unroll
    for (int v = 0; v < VEC; v++) {
        int node = b * VEC + v;
        float dinv = g_dinv[node];
        const float* pa = g_agg2 + (size_t)node * 8;
#pragma unroll
        for (int k = 0; k < D_ENC; k++)
            r[v * D_ENC + k] = gelu_exact(fmaf(dinv, pa[k], sb2[k]));
    }

    float enc[30];
#pragma unroll
    for (int o = 0; o < 30; o++) {
        float s = sbe[o];
#pragma unroll
        for (int j = 0; j < 30; j++) s = fmaf(r[j], sWe[j * 30 + o], s);
        enc[o] = s;
    }

    float* px1 = out + (size_t)b * 7;
#pragma unroll
    for (int o = 0; o < 7; o++) {
        float s = sbr[o];
#pragma unroll
        for (int j = 0; j < 30; j++) s = fmaf(enc[j], sWr[j * 7 + o], s);
        px1[o] = s;
    }

    float* pe = out + (size_t)B_ROWS * 7 + (size_t)b * 30;
#pragma unroll
    for (int o = 0; o < 30; o++) pe[o] = enc[o];

#pragma unroll
    for (int j = 0; j < 30; j++) r[j] = gelu_exact(enc[j]);
    float* po = out + (size_t)B_ROWS * 37 + (size_t)b * 60;
#pragma unroll
    for (int o = 0; o < 60; o++) {
        float s = sbd[o];
#pragma unroll
        for (int j = 0; j < 30; j++) s = fmaf(r[j], sWd[j * 60 + o], s);
        po[o] = s;
    }
}

// ---------------------------------------------------------------- launch

extern "C" void kernel_launch(void* const* d_in, const int* in_sizes, int n_in,
                              void* d_out, int out_size) {
    const float* x  = (const float*)d_in[0];
    const int*   ei = (const int*)  d_in[1];
    const float* W1 = (const float*)d_in[2];
    const float* b1 = (const float*)d_in[3];
    const float* W2 = (const float*)d_in[4];
    const float* b2 = (const float*)d_in[5];
    const float* We = (const float*)d_in[6];
    const float* be = (const float*)d_in[7];
    const float* Wd = (const float*)d_in[8];
    const float* bd = (const float*)d_in[9];
    const float* Wr = (const float*)d_in[10];
    const float* br = (const float*)d_in[11];
    float* out = (float*)d_out;

    const int TB = 256;
    int gN = (N_NODES + TB - 1) / TB;
    int gE = (E_EDGES + TB - 1) / TB;
    int gB = (B_ROWS + TB - 1) / TB;

    k_zero_deg<<<gN, TB>>>();
    k_deg<<<gE, TB>>>(ei);
    k_node1<<<gN, TB>>>(x, W1);
    k_edge1<0><<<gE, TB>>>(ei);
    k_edge1<1><<<gE, TB>>>(ei);
    k_node2<<<gN, TB>>>(b1, W2);
    k_edge2<<<gE, TB>>>(ei);
    k_final<<<gB, TB>>>(b2, We, be, Wd, bd, Wr, br, out);
}

// round 4
// speedup vs baseline: 1.8004x; 1.3059x over previous
#include <cuda_runtime.h>
#include <cuda_fp16.h>
#include <cuda_bf16.h>

#define N_NODES 1200000
#define E_EDGES 12000000
#define D_IN    10
#define D_H     20
#define D_ENC   5
#define VEC     6
#define B_ROWS  200000

// ---- scratch (device globals; allocation-free) ----
__device__ float  g_deg [N_NODES];
__device__ float  g_dinv[N_NODES];
// layer-1 gather source: h*dinv, fp16, tight 20-half rows (40B, 8B-aligned)
__device__ __half g_h1  [N_NODES * 20];
// layer-1 accumulator: fp16, 24-half rows (48B, 16B-aligned for red.v4.f16x2)
__device__ __half g_acc1[N_NODES * 24];
// layer-2 gather source: h2*dinv, fp16, 8-half rows (16B)
__device__ __half g_h2  [N_NODES * 8];
// layer-2 accumulator: fp16, 8-half rows (16B)
__device__ __half g_acc2[N_NODES * 8];

__device__ __forceinline__ float gelu_exact(float v) { return v * normcdff(v); }

__device__ __forceinline__ void red_add_v4h2(__half* p, unsigned a, unsigned b,
                                             unsigned c, unsigned d) {
    asm volatile("red.global.add.noftz.v4.f16x2 [%0], {%1,%2,%3,%4};"
                 :: "l"(p), "r"(a), "r"(b), "r"(c), "r"(d) : "memory");
}
__device__ __forceinline__ void red_add_v2h2(__half* p, unsigned a, unsigned b) {
    asm volatile("red.global.add.noftz.v2.f16x2 [%0], {%1,%2};"
                 :: "l"(p), "r"(a), "r"(b) : "memory");
}
__device__ __forceinline__ void red_add_h2(__half* p, unsigned a) {
    asm volatile("red.global.add.noftz.f16x2 [%0], %1;"
                 :: "l"(p), "r"(a) : "memory");
}

// ---------------------------------------------------------------- kernels

__global__ void k_zero_deg() {
    int i = blockIdx.x * blockDim.x + threadIdx.x;
    if (i < N_NODES) g_deg[i] = 0.0f;
}

__global__ void k_deg(const int* __restrict__ ei) {
    int e = blockIdx.x * blockDim.x + threadIdx.x;
    if (e < E_EDGES) {
        int dst = __ldcs(ei + E_EDGES + e);
        atomicAdd(&g_deg[dst], 1.0f);
    }
}

// dinv; h = (x+po)@W1 * dinv ; write fp16 gather row + fp16 acc init (self term)
__global__ void k_node1(const float* __restrict__ x, const float* __restrict__ W1) {
    __shared__ float sW[D_IN * D_H];
    if (threadIdx.x < D_IN * D_H) sW[threadIdx.x] = W1[threadIdx.x];
    __syncthreads();

    int i = blockIdx.x * blockDim.x + threadIdx.x;
    if (i >= N_NODES) return;

    float dinv = rsqrtf(g_deg[i] + 1.0f);
    g_dinv[i] = dinv;

    float xi[D_IN];
#pragma unroll
    for (int j = 0; j < D_IN; j++) xi[j] = x[(size_t)i * D_IN + j] + sinf((float)j);

    float h[D_H];
#pragma unroll
    for (int k = 0; k < D_H; k++) {
        float s = 0.0f;
#pragma unroll
        for (int j = 0; j < D_IN; j++) s = fmaf(xi[j], sW[j * D_H + k], s);
        h[k] = s * dinv;   // pre-scaled by source dinv
    }

    __half hv[24];
#pragma unroll
    for (int k = 0; k < D_H; k++) hv[k] = __float2half_rn(h[k]);
#pragma unroll
    for (int k = D_H; k < 24; k++) hv[k] = __float2half_rn(0.f);

    // gather source: tight 40B row, 8B-aligned -> 5x uint2
    __half* hp = &g_h1[(size_t)i * 20];
    const uint2* src2 = reinterpret_cast<const uint2*>(hv);
#pragma unroll
    for (int q = 0; q < 5; q++) reinterpret_cast<uint2*>(hp)[q] = src2[q];

    // accumulator init: 48B row, 16B-aligned -> 3x uint4
    __half* ap = &g_acc1[(size_t)i * 24];
    const uint4* src4 = reinterpret_cast<const uint4*>(hv);
#pragma unroll
    for (int q = 0; q < 3; q++) reinterpret_cast<uint4*>(ap)[q] = src4[q];
}

// layer-1 edge scatter: single pass, pure gather -> fp16 RED
__global__ void k_edge1(const int* __restrict__ ei) {
    int e = blockIdx.x * blockDim.x + threadIdx.x;
    if (e >= E_EDGES) return;
    int s = __ldcs(ei + e);
    int d = __ldcs(ei + E_EDGES + e);

    const __half* hp = &g_h1[(size_t)s * 20];
    uint2 a0 = reinterpret_cast<const uint2*>(hp)[0];
    uint2 a1 = reinterpret_cast<const uint2*>(hp)[1];
    uint2 a2 = reinterpret_cast<const uint2*>(hp)[2];
    uint2 a3 = reinterpret_cast<const uint2*>(hp)[3];
    uint2 a4 = reinterpret_cast<const uint2*>(hp)[4];

    __half* ad = &g_acc1[(size_t)d * 24];
    red_add_v4h2(ad,      a0.x, a0.y, a1.x, a1.y);
    red_add_v4h2(ad + 8,  a2.x, a2.y, a3.x, a3.y);
    red_add_v2h2(ad + 16, a4.x, a4.y);
}

// h1 = gelu(dinv*acc1 + b1); h2 = (h1@W2)*dinv ; write fp16 h2 + fp16 acc2 init
__global__ void k_node2(const float* __restrict__ b1, const float* __restrict__ W2) {
    __shared__ float sW[D_H * D_ENC];
    __shared__ float sb[D_H];
    if (threadIdx.x < D_H * D_ENC) sW[threadIdx.x] = W2[threadIdx.x];
    if (threadIdx.x < D_H) sb[threadIdx.x] = b1[threadIdx.x];
    __syncthreads();

    int i = blockIdx.x * blockDim.x + threadIdx.x;
    if (i >= N_NODES) return;

    float dinv = g_dinv[i];

    const __half* ap = &g_acc1[(size_t)i * 24];
    uint4 w[3];
#pragma unroll
    for (int q = 0; q < 3; q++) w[q] = reinterpret_cast<const uint4*>(ap)[q];
    const __half2* h2v = reinterpret_cast<const __half2*>(w);

    float h1[D_H];
#pragma unroll
    for (int k = 0; k < D_H / 2; k++) {
        float2 f = __half22float2(h2v[k]);
        h1[2*k]   = gelu_exact(fmaf(dinv, f.x, sb[2*k]));
        h1[2*k+1] = gelu_exact(fmaf(dinv, f.y, sb[2*k+1]));
    }

    float h2[D_ENC];
#pragma unroll
    for (int c = 0; c < D_ENC; c++) {
        float s = 0.0f;
#pragma unroll
        for (int k = 0; k < D_H; k++) s = fmaf(h1[k], sW[k * D_ENC + c], s);
        h2[c] = s * dinv;   // pre-scaled by source dinv
    }

    __half hv[8];
#pragma unroll
    for (int k = 0; k < D_ENC; k++) hv[k] = __float2half_rn(h2[k]);
#pragma unroll
    for (int k = D_ENC; k < 8; k++) hv[k] = __float2half_rn(0.f);
    uint4 pack = *reinterpret_cast<const uint4*>(hv);
    *reinterpret_cast<uint4*>(&g_h2  [(size_t)i * 8]) = pack;
    *reinterpret_cast<uint4*>(&g_acc2[(size_t)i * 8]) = pack;
}

// layer-2 edge scatter: pure gather -> fp16 RED
__global__ void k_edge2(const int* __restrict__ ei) {
    int e = blockIdx.x * blockDim.x + threadIdx.x;
    if (e >= E_EDGES) return;
    int s = __ldcs(ei + e);
    int d = __ldcs(ei + E_EDGES + e);

    uint4 w = *reinterpret_cast<const uint4*>(&g_h2[(size_t)s * 8]);

    __half* ad = &g_acc2[(size_t)d * 8];
    red_add_v2h2(ad, w.x, w.y);
    red_add_h2(ad + 4, w.z);   // halfs 4,5 (5 is zero pad on both sides)
}

// epilogue
__global__ void k_final(const float* __restrict__ b2,
                        const float* __restrict__ We, const float* __restrict__ be,
                        const float* __restrict__ Wd, const float* __restrict__ bd,
                        const float* __restrict__ Wr, const float* __restrict__ br,
                        float* __restrict__ out) {
    __shared__ float sWe[30 * 30];
    __shared__ float sWd[30 * 60];
    __shared__ float sWr[30 * 7];
    __shared__ float sbe[30], sbd[60], sbr[7], sb2[5];

    for (int t = threadIdx.x; t < 900;  t += blockDim.x) sWe[t] = We[t];
    for (int t = threadIdx.x; t < 1800; t += blockDim.x) sWd[t] = Wd[t];
    for (int t = threadIdx.x; t < 210;  t += blockDim.x) sWr[t] = Wr[t];
    if (threadIdx.x < 30) sbe[threadIdx.x] = be[threadIdx.x];
    if (threadIdx.x < 60) sbd[threadIdx.x] = bd[threadIdx.x];
    if (threadIdx.x < 7)  sbr[threadIdx.x] = br[threadIdx.x];
    if (threadIdx.x < 5)  sb2[threadIdx.x] = b2[threadIdx.x];
    __syncthreads();

    int b = blockIdx.x * blockDim.x + threadIdx.x;
    if (b >= B_ROWS) return;

    float r[30];
#pragma unroll
    for (int v = 0; v < VEC; v++) {
        int node = b * VEC + v;
        float dinv = g_dinv[node];
        uint4 w = *reinterpret_cast<const uint4*>(&g_acc2[(size_t)node * 8]);
        const __half* hv = reinterpret_cast<const __half*>(&w);
#pragma unroll
        for (int k = 0; k < D_ENC; k++)
            r[v * D_ENC + k] = gelu_exact(fmaf(dinv, __half2float(hv[k]), sb2[k]));
    }

    float enc[30];
#pragma unroll
    for (int o = 0; o < 30; o++) {
        float s = sbe[o];
#pragma unroll
        for (int j = 0; j < 30; j++) s = fmaf(r[j], sWe[j * 30 + o], s);
        enc[o] = s;
    }

    float* px1 = out + (size_t)b * 7;
#pragma unroll
    for (int o = 0; o < 7; o++) {
        float s = sbr[o];
#pragma unroll
        for (int j = 0; j < 30; j++) s = fmaf(enc[j], sWr[j * 7 + o], s);
        px1[o] = s;
    }

    float* pe = out + (size_t)B_ROWS * 7 + (size_t)b * 30;
#pragma unroll
    for (int o = 0; o < 30; o++) pe[o] = enc[o];

#pragma unroll
    for (int j = 0; j < 30; j++) r[j] = gelu_exact(enc[j]);
    float* po = out + (size_t)B_ROWS * 37 + (size_t)b * 60;
#pragma unroll
    for (int o = 0; o < 60; o++) {
        float s = sbd[o];
#pragma unroll
        for (int j = 0; j < 30; j++) s = fmaf(r[j], sWd[j * 60 + o], s);
        po[o] = s;
    }
}

// ---------------------------------------------------------------- launch

extern "C" void kernel_launch(void* const* d_in, const int* in_sizes, int n_in,
                              void* d_out, int out_size) {
    const float* x  = (const float*)d_in[0];
    const int*   ei = (const int*)  d_in[1];
    const float* W1 = (const float*)d_in[2];
    const float* b1 = (const float*)d_in[3];
    const float* W2 = (const float*)d_in[4];
    const float* b2 = (const float*)d_in[5];
    const float* We = (const float*)d_in[6];
    const float* be = (const float*)d_in[7];
    const float* Wd = (const float*)d_in[8];
    const float* bd = (const float*)d_in[9];
    const float* Wr = (const float*)d_in[10];
    const float* br = (const float*)d_in[11];
    float* out = (float*)d_out;

    const int TB = 256;
    int gN = (N_NODES + TB - 1) / TB;
    int gE = (E_EDGES + TB - 1) / TB;
    int gB = (B_ROWS + TB - 1) / TB;

    k_zero_deg<<<gN, TB>>>();
    k_deg<<<gE, TB>>>(ei);
    k_node1<<<gN, TB>>>(x, W1);
    k_edge1<<<gE, TB>>>(ei);
    k_node2<<<gN, TB>>>(b1, W2);
    k_edge2<<<gE, TB>>>(ei);
    k_final<<<gB, TB>>>(b2, We, be, Wd, bd, Wr, br, out);
}

// round 6
// speedup vs baseline: 1.9343x; 1.0744x over previous
#include <cuda_runtime.h>
#include <cuda_fp16.h>
#include <cuda_bf16.h>

#define N_NODES 1200000
#define E_EDGES 12000000
#define D_IN    10
#define D_H     20
#define D_ENC   5
#define VEC     6
#define B_ROWS  200000

// ---- scratch (device globals; allocation-free) ----
__device__ float  g_deg [N_NODES];
__device__ float  g_dinv[N_NODES];
// layer-1 gather source: h*dinv, fp16, tight 20-half rows (40B, 8B-aligned)
__device__ __half g_h1  [N_NODES * 20];
// layer-1 accumulator: fp16, 24-half rows (48B, 16B-aligned for red.v4.f16x2)
__device__ __half g_acc1[N_NODES * 24];
// layer-2 gather source: h2*dinv, fp16, 8-half rows (16B, halfs 5-7 zero)
__device__ __half g_h2  [N_NODES * 8];
// layer-2 accumulator: fp16, 8-half rows (16B) -> one v4 RED
__device__ __half g_acc2[N_NODES * 8];

__device__ __forceinline__ float gelu_exact(float v) { return v * normcdff(v); }

__device__ __forceinline__ void red_add_v4h2(__half* p, unsigned a, unsigned b,
                                             unsigned c, unsigned d) {
    asm volatile("red.global.add.noftz.v4.f16x2 [%0], {%1,%2,%3,%4};"
                 :: "l"(p), "r"(a), "r"(b), "r"(c), "r"(d) : "memory");
}
__device__ __forceinline__ void red_add_v2h2(__half* p, unsigned a, unsigned b) {
    asm volatile("red.global.add.noftz.v2.f16x2 [%0], {%1,%2};"
                 :: "l"(p), "r"(a), "r"(b) : "memory");
}

// ---------------------------------------------------------------- kernels

__global__ void k_zero_deg() {
    int i = blockIdx.x * blockDim.x + threadIdx.x;
    if (i < N_NODES) g_deg[i] = 0.0f;
}

__global__ void k_deg(const int* __restrict__ ei) {
    int e = blockIdx.x * blockDim.x + threadIdx.x;
    if (e < E_EDGES) {
        int dst = __ldcs(ei + E_EDGES + e);
        atomicAdd(&g_deg[dst], 1.0f);
    }
}

// dinv; h = (x+po)@W1 * dinv ; write fp16 gather row + fp16 acc init (self term)
__global__ void k_node1(const float* __restrict__ x, const float* __restrict__ W1) {
    __shared__ float sW[D_IN * D_H];
    if (threadIdx.x < D_IN * D_H) sW[threadIdx.x] = W1[threadIdx.x];
    __syncthreads();

    int i = blockIdx.x * blockDim.x + threadIdx.x;
    if (i >= N_NODES) return;

    float dinv = rsqrtf(g_deg[i] + 1.0f);
    g_dinv[i] = dinv;

    float xi[D_IN];
#pragma unroll
    for (int j = 0; j < D_IN; j++) xi[j] = x[(size_t)i * D_IN + j] + sinf((float)j);

    float h[D_H];
#pragma unroll
    for (int k = 0; k < D_H; k++) {
        float s = 0.0f;
#pragma unroll
        for (int j = 0; j < D_IN; j++) s = fmaf(xi[j], sW[j * D_H + k], s);
        h[k] = s * dinv;   // pre-scaled by source dinv
    }

    __half hv[24];
#pragma unroll
    for (int k = 0; k < D_H; k++) hv[k] = __float2half_rn(h[k]);
#pragma unroll
    for (int k = D_H; k < 24; k++) hv[k] = __float2half_rn(0.f);

    // gather source: tight 40B row, 8B-aligned -> 5x uint2
    __half* hp = &g_h1[(size_t)i * 20];
    const uint2* src2 = reinterpret_cast<const uint2*>(hv);
#pragma unroll
    for (int q = 0; q < 5; q++) reinterpret_cast<uint2*>(hp)[q] = src2[q];

    // accumulator init: 48B row, 16B-aligned -> 3x uint4
    __half* ap = &g_acc1[(size_t)i * 24];
    const uint4* src4 = reinterpret_cast<const uint4*>(hv);
#pragma unroll
    for (int q = 0; q < 3; q++) reinterpret_cast<uint4*>(ap)[q] = src4[q];
}

// layer-1 edge scatter: gather -> 3 fp16 REDs (v4+v4+v2)
__global__ void k_edge1(const int* __restrict__ ei) {
    int e = blockIdx.x * blockDim.x + threadIdx.x;
    if (e >= E_EDGES) return;
    int s = __ldcs(ei + e);
    int d = __ldcs(ei + E_EDGES + e);

    const __half* hp = &g_h1[(size_t)s * 20];
    uint2 a0 = reinterpret_cast<const uint2*>(hp)[0];
    uint2 a1 = reinterpret_cast<const uint2*>(hp)[1];
    uint2 a2 = reinterpret_cast<const uint2*>(hp)[2];
    uint2 a3 = reinterpret_cast<const uint2*>(hp)[3];
    uint2 a4 = reinterpret_cast<const uint2*>(hp)[4];

    __half* ad = &g_acc1[(size_t)d * 24];
    red_add_v4h2(ad,      a0.x, a0.y, a1.x, a1.y);
    red_add_v4h2(ad + 8,  a2.x, a2.y, a3.x, a3.y);
    red_add_v2h2(ad + 16, a4.x, a4.y);
}

// h1 = gelu(dinv*acc1 + b1); h2 = (h1@W2)*dinv ; write fp16 h2 + fp16 acc2 init
__global__ void k_node2(const float* __restrict__ b1, const float* __restrict__ W2) {
    __shared__ float sW[D_H * D_ENC];
    __shared__ float sb[D_H];
    if (threadIdx.x < D_H * D_ENC) sW[threadIdx.x] = W2[threadIdx.x];
    if (threadIdx.x < D_H) sb[threadIdx.x] = b1[threadIdx.x];
    __syncthreads();

    int i = blockIdx.x * blockDim.x + threadIdx.x;
    if (i >= N_NODES) return;

    float dinv = g_dinv[i];

    const __half* ap = &g_acc1[(size_t)i * 24];
    uint4 w[3];
#pragma unroll
    for (int q = 0; q < 3; q++) w[q] = reinterpret_cast<const uint4*>(ap)[q];
    const __half2* h2v = reinterpret_cast<const __half2*>(w);

    float h1[D_H];
#pragma unroll
    for (int k = 0; k < D_H / 2; k++) {
        float2 f = __half22float2(h2v[k]);
        h1[2*k]   = gelu_exact(fmaf(dinv, f.x, sb[2*k]));
        h1[2*k+1] = gelu_exact(fmaf(dinv, f.y, sb[2*k+1]));
    }

    float h2[D_ENC];
#pragma unroll
    for (int c = 0; c < D_ENC; c++) {
        float s = 0.0f;
#pragma unroll
        for (int k = 0; k < D_H; k++) s = fmaf(h1[k], sW[k * D_ENC + c], s);
        h2[c] = s * dinv;   // pre-scaled by source dinv
    }

    __half hv[8];
#pragma unroll
    for (int k = 0; k < D_ENC; k++) hv[k] = __float2half_rn(h2[k]);
#pragma unroll
    for (int k = D_ENC; k < 8; k++) hv[k] = __float2half_rn(0.f);
    uint4 pack = *reinterpret_cast<const uint4*>(hv);
    *reinterpret_cast<uint4*>(&g_h2  [(size_t)i * 8]) = pack;
    *reinterpret_cast<uint4*>(&g_acc2[(size_t)i * 8]) = pack;
}

// layer-2 edge scatter: gather -> single v4 fp16 RED (pads are zero, adds exact)
__global__ void k_edge2(const int* __restrict__ ei) {
    int e = blockIdx.x * blockDim.x + threadIdx.x;
    if (e >= E_EDGES) return;
    int s = __ldcs(ei + e);
    int d = __ldcs(ei + E_EDGES + e);

    uint4 w = *reinterpret_cast<const uint4*>(&g_h2[(size_t)s * 8]);
    red_add_v4h2(&g_acc2[(size_t)d * 8], w.x, w.y, w.z, w.w);
}

// epilogue
__global__ void k_final(const float* __restrict__ b2,
                        const float* __restrict__ We, const float* __restrict__ be,
                        const float* __restrict__ Wd, const float* __restrict__ bd,
                        const float* __restrict__ Wr, const float* __restrict__ br,
                        float* __restrict__ out) {
    __shared__ float sWe[30 * 30];
    __shared__ float sWd[30 * 60];
    __shared__ float sWr[30 * 7];
    __shared__ float sbe[30], sbd[60], sbr[7], sb2[5];

    for (int t = threadIdx.x; t < 900;  t += blockDim.x) sWe[t] = We[t];
    for (int t = threadIdx.x; t < 1800; t += blockDim.x) sWd[t] = Wd[t];
    for (int t = threadIdx.x; t < 210;  t += blockDim.x) sWr[t] = Wr[t];
    if (threadIdx.x < 30) sbe[threadIdx.x] = be[threadIdx.x];
    if (threadIdx.x < 60) sbd[threadIdx.x] = bd[threadIdx.x];
    if (threadIdx.x < 7)  sbr[threadIdx.x] = br[threadIdx.x];
    if (threadIdx.x < 5)  sb2[threadIdx.x] = b2[threadIdx.x];
    __syncthreads();

    int b = blockIdx.x * blockDim.x + threadIdx.x;
    if (b >= B_ROWS) return;

    float r[30];
#pragma unroll
    for (int v = 0; v < VEC; v++) {
        int node = b * VEC + v;
        float dinv = g_dinv[node];
        uint4 w = *reinterpret_cast<const uint4*>(&g_acc2[(size_t)node * 8]);
        const __half* hv = reinterpret_cast<const __half*>(&w);
#pragma unroll
        for (int k = 0; k < D_ENC; k++)
            r[v * D_ENC + k] = gelu_exact(fmaf(dinv, __half2float(hv[k]), sb2[k]));
    }

    float enc[30];
#pragma unroll
    for (int o = 0; o < 30; o++) {
        float s = sbe[o];
#pragma unroll
        for (int j = 0; j < 30; j++) s = fmaf(r[j], sWe[j * 30 + o], s);
        enc[o] = s;
    }

    float* px1 = out + (size_t)b * 7;
#pragma unroll
    for (int o = 0; o < 7; o++) {
        float s = sbr[o];
#pragma unroll
        for (int j = 0; j < 30; j++) s = fmaf(enc[j], sWr[j * 7 + o], s);
        px1[o] = s;
    }

    float* pe = out + (size_t)B_ROWS * 7 + (size_t)b * 30;
#pragma unroll
    for (int o = 0; o < 30; o++) pe[o] = enc[o];

#pragma unroll
    for (int j = 0; j < 30; j++) r[j] = gelu_exact(enc[j]);
    float* po = out + (size_t)B_ROWS * 37 + (size_t)b * 60;
#pragma unroll
    for (int o = 0; o < 60; o++) {
        float s = sbd[o];
#pragma unroll
        for (int j = 0; j < 30; j++) s = fmaf(r[j], sWd[j * 60 + o], s);
        po[o] = s;
    }
}

// ---------------------------------------------------------------- launch

extern "C" void kernel_launch(void* const* d_in, const int* in_sizes, int n_in,
                              void* d_out, int out_size) {
    const float* x  = (const float*)d_in[0];
    const int*   ei = (const int*)  d_in[1];
    const float* W1 = (const float*)d_in[2];
    const float* b1 = (const float*)d_in[3];
    const float* W2 = (const float*)d_in[4];
    const float* b2 = (const float*)d_in[5];
    const float* We = (const float*)d_in[6];
    const float* be = (const float*)d_in[7];
    const float* Wd = (const float*)d_in[8];
    const float* bd = (const float*)d_in[9];
    const float* Wr = (const float*)d_in[10];
    const float* br = (const float*)d_in[11];
    float* out = (float*)d_out;

    const int TB = 256;
    int gN = (N_NODES + TB - 1) / TB;
    int gE = (E_EDGES + TB - 1) / TB;
    int gB = (B_ROWS + TB - 1) / TB;

    k_zero_deg<<<gN, TB>>>();
    k_deg<<<gE, TB>>>(ei);
    k_node1<<<gN, TB>>>(x, W1);
    k_edge1<<<gE, TB>>>(ei);
    k_node2<<<gN, TB>>>(b1, W2);
    k_edge2<<<gE, TB>>>(ei);
    k_final<<<gB, TB>>>(b2, We, be, Wd, bd, Wr, br, out);
}